// round 10
// baseline (speedup 1.0000x reference)
#include <cuda_runtime.h>
#include <math.h>

#define NVERT 289
#define NFACE 512
#define IMGS  128
#define KF    8
#define MAXC  64
#define NTH   256

#define KEY_INVALID 0xFFFFFFFFFFFFFFFFull

// Precomputed per-face data (written by setup_kernel, read by raster_kernel).
__device__ float4 g_bb[NFACE];   // xmin,xmax,ymin,ymax (margin included)
__device__ float4 g_A[NFACE];    // ax,ay,z0,1/area_s
__device__ float4 g_B[NFACE];    // bx,by,z1,1/Lab
__device__ float4 g_C[NFACE];    // cx,cy,z2,1/Lbc
__device__ float4 g_E[NFACE];    // 1/Lca, z1z2, z0z2, z0z1
__device__ float4 g_U[NFACE];    // u0,u1,u2,-
__device__ float4 g_V[NFACE];    // v0,v1,v2,-

// ---------------------------------------------------------------------------
// Face connectivity: replicate _build_faces(17,17) analytically.
// ---------------------------------------------------------------------------
__device__ __forceinline__ void face_vids(int f, int& i0, int& i1, int& i2) {
    int grp = f >> 6;
    int g   = f & 63;
    int nyi = g >> 3;
    int nxi = g & 7;
    int ny = (grp >= 4) ? (1 + 2 * nyi) : (2 * nyi);
    int nx;
    if (grp == 0 || grp == 1 || grp == 6 || grp == 7) nx = 1 + 2 * nxi;
    else                                              nx = 2 * nxi;
    int a  = ny * 17 + nx;
    int r  = a + 1;
    int d  = a + 17;
    int dr = a + 18;
    switch (grp) {
        case 0: i0 = r;  i1 = a; i2 = d;  break;
        case 1: i0 = r;  i1 = d; i2 = dr; break;
        case 2: i0 = r;  i1 = a; i2 = dr; break;
        case 3: i0 = dr; i1 = a; i2 = d;  break;
        case 4: i0 = r;  i1 = a; i2 = d;  break;
        case 5: i0 = r;  i1 = d; i2 = dr; break;
        case 6: i0 = r;  i1 = a; i2 = dr; break;
        default:i0 = dr; i1 = a; i2 = d;  break;
    }
}

// ===========================================================================
// Kernel 1: vertex transform + face setup (runs once, 1 block).
// ===========================================================================
__global__ void __launch_bounds__(NFACE)
setup_kernel(const float* __restrict__ xy_off,
             const float* __restrict__ z_grid,
             const float* __restrict__ R_in,
             const float* __restrict__ T_in,
             const float* __restrict__ R_out,
             const float* __restrict__ T_out) {
    __shared__ float s_vx[NVERT], s_vy[NVERT], s_vz[NVERT];
    const int tid = threadIdx.x;

    if (tid < NVERT) {
        float ri[9], ro[9], ti[3], to[3];
#pragma unroll
        for (int i = 0; i < 9; i++) { ri[i] = __ldg(R_in + i); ro[i] = __ldg(R_out + i); }
#pragma unroll
        for (int i = 0; i < 3; i++) { ti[i] = __ldg(T_in + i); to[i] = __ldg(T_out + i); }
        const float SCALE = 0.57735026918962576451f;   // tan(30deg)
        const float SINV  = 1.7320508075688772935f;    // 1/SCALE
        int v = tid;
        float xs = -1.0f + (float)(v % 17) * 0.125f;
        float ys = -1.0f + (float)(v / 17) * 0.125f;
        float gx = (xs + __ldg(xy_off + 2 * v)) * SCALE;
        float gy = (ys + __ldg(xy_off + 2 * v + 1)) * SCALE;
        float zg = __ldg(z_grid + v);
        float sx = gx * zg, sy = gy * zg, sz = zg;
        float p0 = sx - ti[0], p1 = sy - ti[1], p2 = sz - ti[2];
        float w0 = ri[0] * p0 + ri[1] * p1 + ri[2] * p2;
        float w1 = ri[3] * p0 + ri[4] * p1 + ri[5] * p2;
        float w2 = ri[6] * p0 + ri[7] * p1 + ri[8] * p2;
        float vx = ro[0] * w0 + ro[3] * w1 + ro[6] * w2 + to[0];
        float vy = ro[1] * w0 + ro[4] * w1 + ro[7] * w2 + to[1];
        float vz = ro[2] * w0 + ro[5] * w1 + ro[8] * w2 + to[2];
        float zden = (vz >= 0.0f) ? fmaxf(vz, 0.01f) : fminf(vz, -0.01f);
        float rz = __frcp_rn(zden);
        s_vx[v] = SINV * vx * rz;
        s_vy[v] = SINV * vy * rz;
        s_vz[v] = vz;
    }
    __syncthreads();

    const float M = 0.0105f;   // blur reach sqrt(1e-4)=0.01 + fp margin
    int f = tid;               // blockDim == NFACE
    int i0, i1, i2;
    face_vids(f, i0, i1, i2);
    float ax = s_vx[i0], ay = s_vy[i0], z0 = s_vz[i0];
    float bx = s_vx[i1], by = s_vy[i1], z1 = s_vz[i1];
    float cx = s_vx[i2], cy = s_vy[i2], z2 = s_vz[i2];
    float area = (bx - ax) * (cy - ay) - (by - ay) * (cx - ax);
    float area_s = (fabsf(area) < 1e-8f) ? 1e-8f : area;
    float dabx = bx - ax, daby = by - ay;
    float dbcx = cx - bx, dbcy = cy - by;
    float dcax = ax - cx, dcay = ay - cy;
    float Lab = fmaxf(dabx * dabx + daby * daby, 1e-12f);
    float Lbc = fmaxf(dbcx * dbcx + dbcy * dbcy, 1e-12f);
    float Lca = fmaxf(dcax * dcax + dcay * dcay, 1e-12f);
    g_bb[f] = make_float4(fminf(ax, fminf(bx, cx)) - M,
                          fmaxf(ax, fmaxf(bx, cx)) + M,
                          fminf(ay, fminf(by, cy)) - M,
                          fmaxf(ay, fmaxf(by, cy)) + M);
    g_A[f] = make_float4(ax, ay, z0, __frcp_rn(area_s));
    g_B[f] = make_float4(bx, by, z1, __frcp_rn(Lab));
    g_C[f] = make_float4(cx, cy, z2, __frcp_rn(Lbc));
    g_E[f] = make_float4(__frcp_rn(Lca), z1 * z2, z0 * z2, z0 * z1);
    g_U[f] = make_float4(1.0f - (float)(i0 % 17) * 0.0625f,
                         1.0f - (float)(i1 % 17) * 0.0625f,
                         1.0f - (float)(i2 % 17) * 0.0625f, 0.0f);
    g_V[f] = make_float4((float)(i0 / 17) * 0.0625f,
                         (float)(i1 / 17) * 0.0625f,
                         (float)(i2 / 17) * 0.0625f, 0.0f);
}

// ===========================================================================
// Kernel 2: per-tile raster + soft aggregation.
// ===========================================================================
__device__ __forceinline__ float seg_d2_fast(float px, float py,
                                             float sx, float sy,
                                             float ex, float ey, float invL) {
    float dx = ex - sx, dy = ey - sy;
    float t = ((px - sx) * dx + (py - sy) * dy) * invL;
    t = fminf(fmaxf(t, 0.0f), 1.0f);
    float ux = px - (sx + t * dx);
    float uy = py - (sy + t * dy);
    return ux * ux + uy * uy;
}

// Selection-only eval: validity + zpix; seg_d2 lazy (outside pixels only).
__device__ __forceinline__ bool eval_sel(float px, float py,
                                         float4 A, float4 B, float4 C, float4 E,
                                         float& zpix) {
    float w0 = (B.x - px) * (C.y - py) - (B.y - py) * (C.x - px);
    float w1 = (C.x - px) * (A.y - py) - (C.y - py) * (A.x - px);
    float w2 = (A.x - px) * (B.y - py) - (A.y - py) * (B.x - px);
    float b0 = w0 * A.w, b1 = w1 * A.w, b2 = w2 * A.w;
    bool inside = (b0 >= 0.0f) && (b1 >= 0.0f) && (b2 >= 0.0f);
    float n0 = b0 * E.y, n1 = b1 * E.z, n2 = b2 * E.w;
    float den = n0 + n1 + n2;
    den = (fabsf(den) < 1e-10f) ? 1e-10f : den;
    float rden = __frcp_rn(den);
    float c0 = fmaxf(n0 * rden, 0.0f);
    float c1 = fmaxf(n1 * rden, 0.0f);
    float c2 = fmaxf(n2 * rden, 0.0f);
    float rsum = __frcp_rn(fmaxf(c0 + c1 + c2, 1e-10f));
    zpix = (c0 * A.z + c1 * B.z + c2 * C.z) * rsum;
    if (zpix <= 1e-4f) return false;
    if (inside) return true;   // sdist = -d2 < blur always
    float d2 = fminf(fminf(seg_d2_fast(px, py, A.x, A.y, B.x, B.y, B.w),
                           seg_d2_fast(px, py, B.x, B.y, C.x, C.y, C.w)),
                     seg_d2_fast(px, py, C.x, C.y, A.x, A.y, E.x));
    return d2 < 1e-4f;
}

// Full eval for shading.
__device__ __forceinline__ void eval_face(float px, float py,
                                          float4 A, float4 B, float4 C, float4 E,
                                          float& sdist, float& bn0, float& bn1, float& bn2) {
    float w0 = (B.x - px) * (C.y - py) - (B.y - py) * (C.x - px);
    float w1 = (C.x - px) * (A.y - py) - (C.y - py) * (A.x - px);
    float w2 = (A.x - px) * (B.y - py) - (A.y - py) * (B.x - px);
    float b0 = w0 * A.w, b1 = w1 * A.w, b2 = w2 * A.w;
    bool inside = (b0 >= 0.0f) && (b1 >= 0.0f) && (b2 >= 0.0f);
    float n0 = b0 * E.y, n1 = b1 * E.z, n2 = b2 * E.w;
    float den = n0 + n1 + n2;
    den = (fabsf(den) < 1e-10f) ? 1e-10f : den;
    float rden = __frcp_rn(den);
    float c0 = fmaxf(n0 * rden, 0.0f);
    float c1 = fmaxf(n1 * rden, 0.0f);
    float c2 = fmaxf(n2 * rden, 0.0f);
    float rsum = __frcp_rn(fmaxf(c0 + c1 + c2, 1e-10f));
    bn0 = c0 * rsum; bn1 = c1 * rsum; bn2 = c2 * rsum;
    float d2 = fminf(fminf(seg_d2_fast(px, py, A.x, A.y, B.x, B.y, B.w),
                           seg_d2_fast(px, py, B.x, B.y, C.x, C.y, C.w)),
                     seg_d2_fast(px, py, C.x, C.y, A.x, A.y, E.x));
    sdist = inside ? -d2 : d2;
}

__device__ __forceinline__ unsigned long long u64min(unsigned long long a,
                                                     unsigned long long b) {
    return (a < b) ? a : b;
}

__global__ void __launch_bounds__(NTH)
raster_kernel(const float* __restrict__ tex, float* __restrict__ out) {
    __shared__ float4 s_cbb[MAXC];
    __shared__ int    s_idx[MAXC];
    __shared__ int    s_wc[8];

    const int tid  = threadIdx.x;
    const int lane = tid & 31;
    const int wid  = tid >> 5;
    const int sub  = tid & 3;
    const int pixb = tid >> 2;
    const int tx   = blockIdx.x & 15;
    const int ty   = blockIdx.x >> 4;
    const int ix   = tx * 8 + (pixb & 7);
    const int iy   = ty * 8 + (pixb >> 3);
    const float px = 1.0f - (float)(2 * ix + 1) * 0.0078125f;
    const float py = 1.0f - (float)(2 * iy + 1) * 0.0078125f;
    const float pxhi = 1.0f - (float)(2 * (tx * 8) + 1) * 0.0078125f;
    const float pxlo = 1.0f - (float)(2 * (tx * 8 + 7) + 1) * 0.0078125f;
    const float pyhi = 1.0f - (float)(2 * (ty * 8) + 1) * 0.0078125f;
    const float pylo = 1.0f - (float)(2 * (ty * 8 + 7) + 1) * 0.0078125f;

    // --- tile compaction: thread handles faces 2*tid, 2*tid+1 (order-preserving)
    const int f0 = 2 * tid, f1 = f0 + 1;
    float4 b0 = __ldg(&g_bb[f0]);
    float4 b1 = __ldg(&g_bb[f1]);
    bool e0 = (b0.x <= pxhi) && (b0.y >= pxlo) && (b0.z <= pyhi) && (b0.w >= pylo);
    bool e1 = (b1.x <= pxhi) && (b1.y >= pxlo) && (b1.z <= pyhi) && (b1.w >= pylo);
    unsigned em = __ballot_sync(0xffffffffu, e0);
    unsigned om = __ballot_sync(0xffffffffu, e1);
    if (lane == 0) s_wc[wid] = __popc(em) + __popc(om);
    __syncthreads();
    unsigned below = (1u << lane) - 1u;
    int posw = __popc(em & below) + __popc(om & below);
    int base = 0, total = 0;
#pragma unroll
    for (int w = 0; w < 8; w++) {
        if (w < wid) base += s_wc[w];
        total += s_wc[w];
    }
    int p0 = base + posw;
    int p1 = p0 + (e0 ? 1 : 0);
    if (e0 && p0 < MAXC) { s_idx[p0] = f0; s_cbb[p0] = b0; }
    if (e1 && p1 < MAXC) { s_idx[p1] = f1; s_cbb[p1] = b1; }
    __syncthreads();
    if (total > MAXC) total = MAXC;

    // --- selection: 4-way strided; u64 keys (z_bits<<32 | compact_idx) ---
    unsigned long long kk[KF];
#pragma unroll
    for (int k = 0; k < KF; k++) kk[k] = KEY_INVALID;

    for (int i = sub; i < total; i += 4) {
        float4 bb = s_cbb[i];
        if (px < bb.x || px > bb.y || py < bb.z || py > bb.w) continue;
        int f = s_idx[i];
        float4 A = __ldg(&g_A[f]);
        float4 B = __ldg(&g_B[f]);
        float4 C = __ldg(&g_C[f]);
        float4 E = __ldg(&g_E[f]);
        float zpix;
        if (eval_sel(px, py, A, B, C, E, zpix)) {
            unsigned long long key =
                ((unsigned long long)__float_as_uint(zpix) << 32) | (unsigned)i;
            if (key < kk[KF - 1]) {
#pragma unroll
                for (int j = 0; j < KF; j++) {
                    if (key < kk[j]) {
                        unsigned long long t = kk[j]; kk[j] = key; key = t;
                    }
                }
            }
        }
    }

    // --- merge (R8-proven): round 1 full, round 2 min-merge + reversal-aware ---
    {
        unsigned long long bk[KF];
#pragma unroll
        for (int i = 0; i < KF; i++)
            bk[i] = __shfl_xor_sync(0xffffffffu, kk[i], 1);
        unsigned long long ck[KF];
#pragma unroll
        for (int i = 0; i < KF; i++)
            ck[i] = u64min(kk[i], bk[KF - 1 - i]);
#pragma unroll
        for (int d2 = 4; d2 >= 1; d2 >>= 1) {
#pragma unroll
            for (int i = 0; i < KF; i++) {
                if ((i & d2) == 0) {
                    int j = i + d2;
                    unsigned long long lo = u64min(ck[i], ck[j]);
                    unsigned long long hi = (ck[i] < ck[j]) ? ck[j] : ck[i];
                    ck[i] = lo; ck[j] = hi;
                }
            }
        }
#pragma unroll
        for (int i = 0; i < KF; i++) kk[i] = ck[i];
    }
    {
        unsigned long long bk[KF];
#pragma unroll
        for (int i = 0; i < KF; i++)
            bk[i] = __shfl_xor_sync(0xffffffffu, kk[i], 2);
#pragma unroll
        for (int i = 0; i < KF; i++)
            kk[i] = u64min(kk[i], bk[KF - 1 - i]);
    }

    // --- softmax prep: set-max (order-independent over lanes' lists) ---
    const float R99 = 0.010101010101010102f;
    float zmax = 1e-10f;
#pragma unroll
    for (int k = 0; k < KF; k++) {
        unsigned zb = (unsigned)(kk[k] >> 32);
        if (zb != 0xFFFFFFFFu)
            zmax = fmaxf(zmax, (100.0f - __uint_as_float(zb)) * R99);
    }
    float delta = __expf((1e-10f - zmax) * 1e4f);

    // Reversal-aware assignment: lane0:{0,4} lane1:{1,5} lane2:{5,1} lane3:{4,0}
    unsigned long long ks0 =
        (sub == 0) ? kk[0] : (sub == 1) ? kk[1] : (sub == 2) ? kk[5] : kk[4];
    unsigned long long ks1 =
        (sub == 0) ? kk[4] : (sub == 1) ? kk[5] : (sub == 2) ? kk[1] : kk[0];

    float sw = 0.0f, sr = 0.0f, sg = 0.0f, sb = 0.0f, sd = 0.0f, ap = 1.0f;
#pragma unroll
    for (int t = 0; t < 2; t++) {
        unsigned long long key = t ? ks1 : ks0;
        if (key == KEY_INVALID) continue;
        int ci = (int)(unsigned)key;
        int f  = s_idx[ci];
        float zsel = __uint_as_float((unsigned)(key >> 32));
        float4 A = __ldg(&g_A[f]);
        float4 B = __ldg(&g_B[f]);
        float4 C = __ldg(&g_C[f]);
        float4 E = __ldg(&g_E[f]);
        float sdist, bn0, bn1, bn2;
        eval_face(px, py, A, B, C, E, sdist, bn0, bn1, bn2);
        float4 U = __ldg(&g_U[f]);
        float4 V = __ldg(&g_V[f]);
        float uu = bn0 * U.x + bn1 * U.y + bn2 * U.z;
        float vv = bn0 * V.x + bn1 * V.y + bn2 * V.z;
        float tx2 = uu * 127.0f;
        float ty2 = (1.0f - vv) * 127.0f;
        float x0f = fminf(fmaxf(floorf(tx2), 0.0f), 127.0f);
        float y0f = fminf(fmaxf(floorf(ty2), 0.0f), 127.0f);
        int x0 = (int)x0f, y0 = (int)y0f;
        int x1 = min(x0 + 1, 127), y1 = min(y0 + 1, 127);
        float wx = tx2 - x0f, wy = ty2 - y0f;
        const float* p00 = tex + (y0 * IMGS + x0) * 3;
        const float* p01 = tex + (y0 * IMGS + x1) * 3;
        const float* p10 = tex + (y1 * IMGS + x0) * 3;
        const float* p11 = tex + (y1 * IMGS + x1) * 3;
        float omwx = 1.0f - wx, omwy = 1.0f - wy;
        float cr = omwy * (omwx * __ldg(p00 + 0) + wx * __ldg(p01 + 0)) +
                   wy   * (omwx * __ldg(p10 + 0) + wx * __ldg(p11 + 0));
        float cg = omwy * (omwx * __ldg(p00 + 1) + wx * __ldg(p01 + 1)) +
                   wy   * (omwx * __ldg(p10 + 1) + wx * __ldg(p11 + 1));
        float cb = omwy * (omwx * __ldg(p00 + 2) + wx * __ldg(p01 + 2)) +
                   wy   * (omwx * __ldg(p10 + 2) + wx * __ldg(p11 + 2));
        float pr  = __frcp_rn(1.0f + __expf(sdist * 1e4f));
        float zin = (100.0f - zsel) * R99;
        float w   = pr * __expf((zin - zmax) * 1e4f);
        sw += w;
        sr += w * cr;
        sg += w * cg;
        sb += w * cb;
        sd += w * zsel;
        ap *= (1.0f - pr);
    }

    // --- quad butterfly reduction ---
#pragma unroll
    for (int d = 1; d <= 2; d <<= 1) {
        sw += __shfl_xor_sync(0xffffffffu, sw, d);
        sr += __shfl_xor_sync(0xffffffffu, sr, d);
        sg += __shfl_xor_sync(0xffffffffu, sg, d);
        sb += __shfl_xor_sync(0xffffffffu, sb, d);
        sd += __shfl_xor_sync(0xffffffffu, sd, d);
        ap *= __shfl_xor_sync(0xffffffffu, ap, d);
    }
    float rdenom = __frcp_rn(sw + delta);

    int o = (iy * IMGS + ix) * 5;
    if (sub == 0) {
        out[o + 0] = sr * rdenom;
        out[o + 4] = (sd + delta * 100.0f) * rdenom;
    } else if (sub == 1) {
        out[o + 1] = sg * rdenom;
    } else if (sub == 2) {
        out[o + 2] = sb * rdenom;
    } else {
        out[o + 3] = 1.0f - ap;
    }
}

extern "C" void kernel_launch(void* const* d_in, const int* in_sizes, int n_in,
                              void* d_out, int out_size) {
    (void)in_sizes; (void)n_in; (void)out_size;
    setup_kernel<<<1, NFACE>>>(
        (const float*)d_in[0],   // xy_offset (1,289,2)
        (const float*)d_in[1],   // z_grid    (1,289,1)
        (const float*)d_in[3],   // R_in      (1,3,3)
        (const float*)d_in[4],   // T_in      (1,3)
        (const float*)d_in[5],   // R_out     (1,3,3)
        (const float*)d_in[6]);  // T_out     (1,3)
    raster_kernel<<<256, NTH>>>(
        (const float*)d_in[2],   // rgb_in    (1,128,128,3)
        (float*)d_out);          // (1,128,128,5) float32
}

// round 11
// speedup vs baseline: 1.3732x; 1.3732x over previous
#include <cuda_runtime.h>
#include <math.h>

#define NVERT 289
#define NFACE 512
#define IMGS  128
#define KF    8
#define MAXC  64
#define NTH   256

#define KEY_INVALID 0xFFFFFFFFu

// ---------------------------------------------------------------------------
// Face connectivity: replicate _build_faces(17,17) analytically.
// ---------------------------------------------------------------------------
__device__ __forceinline__ void face_vids(int f, int& i0, int& i1, int& i2) {
    int grp = f >> 6;
    int g   = f & 63;
    int nyi = g >> 3;
    int nxi = g & 7;
    int ny = (grp >= 4) ? (1 + 2 * nyi) : (2 * nyi);
    int nx;
    if (grp == 0 || grp == 1 || grp == 6 || grp == 7) nx = 1 + 2 * nxi;
    else                                              nx = 2 * nxi;
    int a  = ny * 17 + nx;
    int r  = a + 1;
    int d  = a + 17;
    int dr = a + 18;
    switch (grp) {
        case 0: i0 = r;  i1 = a; i2 = d;  break;
        case 1: i0 = r;  i1 = d; i2 = dr; break;
        case 2: i0 = r;  i1 = a; i2 = dr; break;
        case 3: i0 = dr; i1 = a; i2 = d;  break;
        case 4: i0 = r;  i1 = a; i2 = d;  break;
        case 5: i0 = r;  i1 = d; i2 = dr; break;
        case 6: i0 = r;  i1 = a; i2 = dr; break;
        default:i0 = dr; i1 = a; i2 = d;  break;
    }
}

__device__ __forceinline__ float seg_d2_fast(float px, float py,
                                             float sx, float sy,
                                             float ex, float ey, float invL) {
    float dx = ex - sx, dy = ey - sy;
    float t = ((px - sx) * dx + (py - sy) * dy) * invL;
    t = fminf(fmaxf(t, 0.0f), 1.0f);
    float ux = px - (sx + t * dx);
    float uy = py - (sy + t * dy);
    return ux * ux + uy * uy;
}

// Full per-face eval: branch-free, returns validity; outputs sdist, zpix, bary.
__device__ __forceinline__ bool eval_full(float px, float py,
                                          float4 A, float4 B, float4 C, float4 E,
                                          float& sdist, float& zpix,
                                          float& bn0, float& bn1, float& bn2) {
    float w0 = (B.x - px) * (C.y - py) - (B.y - py) * (C.x - px);
    float w1 = (C.x - px) * (A.y - py) - (C.y - py) * (A.x - px);
    float w2 = (A.x - px) * (B.y - py) - (A.y - py) * (B.x - px);
    float b0 = w0 * A.w, b1 = w1 * A.w, b2 = w2 * A.w;
    bool inside = (b0 >= 0.0f) && (b1 >= 0.0f) && (b2 >= 0.0f);
    float n0 = b0 * E.y, n1 = b1 * E.z, n2 = b2 * E.w;
    float den = n0 + n1 + n2;
    den = (fabsf(den) < 1e-10f) ? 1e-10f : den;
    float rden = __frcp_rn(den);
    float c0 = fmaxf(n0 * rden, 0.0f);
    float c1 = fmaxf(n1 * rden, 0.0f);
    float c2 = fmaxf(n2 * rden, 0.0f);
    float rsum = __frcp_rn(fmaxf(c0 + c1 + c2, 1e-10f));
    zpix = (c0 * A.z + c1 * B.z + c2 * C.z) * rsum;
    bn0 = c0 * rsum; bn1 = c1 * rsum; bn2 = c2 * rsum;
    float d2 = fminf(fminf(seg_d2_fast(px, py, A.x, A.y, B.x, B.y, B.w),
                           seg_d2_fast(px, py, B.x, B.y, C.x, C.y, C.w)),
                     seg_d2_fast(px, py, C.x, C.y, A.x, A.y, E.x));
    sdist = inside ? -d2 : d2;
    return (sdist < 1e-4f) && (zpix > 1e-4f);
}

__global__ void __launch_bounds__(NTH)
nvp_kernel(const float* __restrict__ xy_off,
           const float* __restrict__ z_grid,
           const float* __restrict__ tex,
           const float* __restrict__ R_in,
           const float* __restrict__ T_in,
           const float* __restrict__ R_out,
           const float* __restrict__ T_out,
           float* __restrict__ out) {
    __shared__ float  s_vx[NVERT], s_vy[NVERT], s_vz[NVERT];
    __shared__ float4 s_A[MAXC], s_B[MAXC], s_C[MAXC], s_E[MAXC];
    __shared__ float4 s_U[MAXC], s_V[MAXC];
    __shared__ int    s_wc[8];

    const int tid  = threadIdx.x;
    const int lane = tid & 31;
    const int wid  = tid >> 5;
    const int sub  = tid & 3;
    const int pixb = tid >> 2;
    const int tx   = blockIdx.x & 15;
    const int ty   = blockIdx.x >> 4;
    const int ix   = tx * 8 + (pixb & 7);
    const int iy   = ty * 8 + (pixb >> 3);
    const float px = 1.0f - (float)(2 * ix + 1) * 0.0078125f;
    const float py = 1.0f - (float)(2 * iy + 1) * 0.0078125f;
    const float pxhi = 1.0f - (float)(2 * (tx * 8) + 1) * 0.0078125f;
    const float pxlo = 1.0f - (float)(2 * (tx * 8 + 7) + 1) * 0.0078125f;
    const float pyhi = 1.0f - (float)(2 * (ty * 8) + 1) * 0.0078125f;
    const float pylo = 1.0f - (float)(2 * (ty * 8 + 7) + 1) * 0.0078125f;

    // --- vertex transform ---
    {
        float ri[9], ro[9], ti[3], to[3];
#pragma unroll
        for (int i = 0; i < 9; i++) { ri[i] = __ldg(R_in + i); ro[i] = __ldg(R_out + i); }
#pragma unroll
        for (int i = 0; i < 3; i++) { ti[i] = __ldg(T_in + i); to[i] = __ldg(T_out + i); }
        const float SCALE = 0.57735026918962576451f;   // tan(30deg)
        const float SINV  = 1.7320508075688772935f;    // 1/SCALE
        for (int v = tid; v < NVERT; v += NTH) {
            float xs = -1.0f + (float)(v % 17) * 0.125f;
            float ys = -1.0f + (float)(v / 17) * 0.125f;
            float gx = (xs + __ldg(xy_off + 2 * v)) * SCALE;
            float gy = (ys + __ldg(xy_off + 2 * v + 1)) * SCALE;
            float zg = __ldg(z_grid + v);
            float sx = gx * zg, sy = gy * zg, sz = zg;
            float p0 = sx - ti[0], p1 = sy - ti[1], p2 = sz - ti[2];
            float w0 = ri[0] * p0 + ri[1] * p1 + ri[2] * p2;
            float w1 = ri[3] * p0 + ri[4] * p1 + ri[5] * p2;
            float w2 = ri[6] * p0 + ri[7] * p1 + ri[8] * p2;
            float vx = ro[0] * w0 + ro[3] * w1 + ro[6] * w2 + to[0];
            float vy = ro[1] * w0 + ro[4] * w1 + ro[7] * w2 + to[1];
            float vz = ro[2] * w0 + ro[5] * w1 + ro[8] * w2 + to[2];
            float zden = (vz >= 0.0f) ? fmaxf(vz, 0.01f) : fminf(vz, -0.01f);
            float rz = __frcp_rn(zden);
            s_vx[v] = SINV * vx * rz;
            s_vy[v] = SINV * vy * rz;
            s_vz[v] = vz;
        }
    }
    __syncthreads();

    // --- face setup + single-sync order-preserving pair compaction ---
    // Thread handles faces 2*tid, 2*tid+1. Bbox (with margin) decides tile
    // membership; accepted faces are written fully-setup into compact slots.
    const float M = 0.0105f;   // blur reach sqrt(1e-4)=0.01 + fp margin
    int total = 0;
    {
        const int f0 = 2 * tid, f1 = f0 + 1;
        int a0, a1, a2, b0i, b1i, b2i;
        face_vids(f0, a0, a1, a2);
        face_vids(f1, b0i, b1i, b2i);
        float ax0 = s_vx[a0], ay0 = s_vy[a0], az0 = s_vz[a0];
        float bx0 = s_vx[a1], by0 = s_vy[a1], bz0 = s_vz[a1];
        float cx0 = s_vx[a2], cy0 = s_vy[a2], cz0 = s_vz[a2];
        float ax1 = s_vx[b0i], ay1 = s_vy[b0i], az1 = s_vz[b0i];
        float bx1 = s_vx[b1i], by1 = s_vy[b1i], bz1 = s_vz[b1i];
        float cx1 = s_vx[b2i], cy1 = s_vy[b2i], cz1 = s_vz[b2i];

        float xm0 = fminf(ax0, fminf(bx0, cx0)) - M;
        float xM0 = fmaxf(ax0, fmaxf(bx0, cx0)) + M;
        float ym0 = fminf(ay0, fminf(by0, cy0)) - M;
        float yM0 = fmaxf(ay0, fmaxf(by0, cy0)) + M;
        float xm1 = fminf(ax1, fminf(bx1, cx1)) - M;
        float xM1 = fmaxf(ax1, fmaxf(bx1, cx1)) + M;
        float ym1 = fminf(ay1, fminf(by1, cy1)) - M;
        float yM1 = fmaxf(ay1, fmaxf(by1, cy1)) + M;
        bool e0 = (xm0 <= pxhi) && (xM0 >= pxlo) && (ym0 <= pyhi) && (yM0 >= pylo);
        bool e1 = (xm1 <= pxhi) && (xM1 >= pxlo) && (ym1 <= pyhi) && (yM1 >= pylo);

        unsigned em = __ballot_sync(0xffffffffu, e0);
        unsigned om = __ballot_sync(0xffffffffu, e1);
        if (lane == 0) s_wc[wid] = __popc(em) + __popc(om);
        __syncthreads();
        unsigned below = (1u << lane) - 1u;
        int posw = __popc(em & below) + __popc(om & below);
        int base = 0;
#pragma unroll
        for (int w = 0; w < 8; w++) {
            if (w < wid) base += s_wc[w];
            total += s_wc[w];
        }
        int p0 = base + posw;
        int p1 = p0 + (e0 ? 1 : 0);

        if (e0 && p0 < MAXC) {
            float area = (bx0 - ax0) * (cy0 - ay0) - (by0 - ay0) * (cx0 - ax0);
            float area_s = (fabsf(area) < 1e-8f) ? 1e-8f : area;
            float Lab = fmaxf((bx0-ax0)*(bx0-ax0) + (by0-ay0)*(by0-ay0), 1e-12f);
            float Lbc = fmaxf((cx0-bx0)*(cx0-bx0) + (cy0-by0)*(cy0-by0), 1e-12f);
            float Lca = fmaxf((ax0-cx0)*(ax0-cx0) + (ay0-cy0)*(ay0-cy0), 1e-12f);
            s_A[p0] = make_float4(ax0, ay0, az0, __frcp_rn(area_s));
            s_B[p0] = make_float4(bx0, by0, bz0, __frcp_rn(Lab));
            s_C[p0] = make_float4(cx0, cy0, cz0, __frcp_rn(Lbc));
            s_E[p0] = make_float4(__frcp_rn(Lca), bz0 * cz0, az0 * cz0, az0 * bz0);
            s_U[p0] = make_float4(1.0f - (float)(a0 % 17) * 0.0625f,
                                  1.0f - (float)(a1 % 17) * 0.0625f,
                                  1.0f - (float)(a2 % 17) * 0.0625f, 0.0f);
            s_V[p0] = make_float4((float)(a0 / 17) * 0.0625f,
                                  (float)(a1 / 17) * 0.0625f,
                                  (float)(a2 / 17) * 0.0625f, 0.0f);
        }
        if (e1 && p1 < MAXC) {
            float area = (bx1 - ax1) * (cy1 - ay1) - (by1 - ay1) * (cx1 - ax1);
            float area_s = (fabsf(area) < 1e-8f) ? 1e-8f : area;
            float Lab = fmaxf((bx1-ax1)*(bx1-ax1) + (by1-ay1)*(by1-ay1), 1e-12f);
            float Lbc = fmaxf((cx1-bx1)*(cx1-bx1) + (cy1-by1)*(cy1-by1), 1e-12f);
            float Lca = fmaxf((ax1-cx1)*(ax1-cx1) + (ay1-cy1)*(ay1-cy1), 1e-12f);
            s_A[p1] = make_float4(ax1, ay1, az1, __frcp_rn(area_s));
            s_B[p1] = make_float4(bx1, by1, bz1, __frcp_rn(Lab));
            s_C[p1] = make_float4(cx1, cy1, cz1, __frcp_rn(Lbc));
            s_E[p1] = make_float4(__frcp_rn(Lca), bz1 * cz1, az1 * cz1, az1 * bz1);
            s_U[p1] = make_float4(1.0f - (float)(b0i % 17) * 0.0625f,
                                  1.0f - (float)(b1i % 17) * 0.0625f,
                                  1.0f - (float)(b2i % 17) * 0.0625f, 0.0f);
            s_V[p1] = make_float4((float)(b0i / 17) * 0.0625f,
                                  (float)(b1i / 17) * 0.0625f,
                                  (float)(b2i / 17) * 0.0625f, 0.0f);
        }
        __syncthreads();
    }
    if (total > MAXC) total = MAXC;

    // --- selection: branch-free eval of EVERY tile candidate (4-way strided).
    //     u32 keys: top-26 z bits | 6-bit compact idx (order-isomorphic to
    //     (z, face_id) up to 2^-17 relative z ties -> negligible).
    unsigned kk[KF];
#pragma unroll
    for (int k = 0; k < KF; k++) kk[k] = KEY_INVALID;

#pragma unroll 2
    for (int i = sub; i < total; i += 4) {
        float4 A = s_A[i], B = s_B[i], C = s_C[i], E = s_E[i];
        float sdist, zpix, bn0, bn1, bn2;
        bool valid = eval_full(px, py, A, B, C, E, sdist, zpix, bn0, bn1, bn2);
        unsigned key = (__float_as_uint(zpix) & 0xFFFFFFC0u) | (unsigned)i;
        if (valid && key < kk[KF - 1]) {
#pragma unroll
            for (int j = 0; j < KF; j++) {
                if (key < kk[j]) { unsigned t = kk[j]; kk[j] = key; key = t; }
            }
        }
    }

    // --- merge 4 per-lane sorted lists (u32 keys) ---
    // Round 1 (xor 1): full merge + bitonic cleanup.
    {
        unsigned bk[KF];
#pragma unroll
        for (int i = 0; i < KF; i++)
            bk[i] = __shfl_xor_sync(0xffffffffu, kk[i], 1);
        unsigned ck[KF];
#pragma unroll
        for (int i = 0; i < KF; i++)
            ck[i] = min(kk[i], bk[KF - 1 - i]);
#pragma unroll
        for (int d2 = 4; d2 >= 1; d2 >>= 1) {
#pragma unroll
            for (int i = 0; i < KF; i++) {
                if ((i & d2) == 0) {
                    int j = i + d2;
                    unsigned lo = min(ck[i], ck[j]);
                    unsigned hi = max(ck[i], ck[j]);
                    ck[i] = lo; ck[j] = hi;
                }
            }
        }
#pragma unroll
        for (int i = 0; i < KF; i++) kk[i] = ck[i];
    }
    // Round 2 (xor 2): min-merge only; lanes 2,3 hold exact reverse(set).
    {
        unsigned bk[KF];
#pragma unroll
        for (int i = 0; i < KF; i++)
            bk[i] = __shfl_xor_sync(0xffffffffu, kk[i], 2);
#pragma unroll
        for (int i = 0; i < KF; i++)
            kk[i] = min(kk[i], bk[KF - 1 - i]);
    }

    // Reversal-aware assignment (R8-proven): lane0:{0,4} lane1:{1,5}
    // lane2:{5,1} lane3:{4,0} covers the 8-element set exactly once.
    unsigned ks[2];
    ks[0] = (sub == 0) ? kk[0] : (sub == 1) ? kk[1] : (sub == 2) ? kk[5] : kk[4];
    ks[1] = (sub == 0) ? kk[4] : (sub == 1) ? kk[5] : (sub == 2) ? kk[1] : kk[0];

    // --- shade: recompute full-precision z/bary for the 2 assigned faces ---
    const float R99 = 0.010101010101010102f;
    float pr[2], zin[2], zsv[2], cr[2], cg[2], cb[2];
#pragma unroll
    for (int t = 0; t < 2; t++) {
        pr[t] = 0.0f; zin[t] = 0.0f; zsv[t] = 0.0f;
        cr[t] = 0.0f; cg[t] = 0.0f; cb[t] = 0.0f;
        if (ks[t] == KEY_INVALID) continue;
        int ci = (int)(ks[t] & 63u);
        float4 A = s_A[ci], B = s_B[ci], C = s_C[ci], E = s_E[ci];
        float sdist, zpix, bn0, bn1, bn2;
        eval_full(px, py, A, B, C, E, sdist, zpix, bn0, bn1, bn2);
        float4 U = s_U[ci], V = s_V[ci];
        float uu = bn0 * U.x + bn1 * U.y + bn2 * U.z;
        float vv = bn0 * V.x + bn1 * V.y + bn2 * V.z;
        float tx2 = uu * 127.0f;
        float ty2 = (1.0f - vv) * 127.0f;
        float x0f = fminf(fmaxf(floorf(tx2), 0.0f), 127.0f);
        float y0f = fminf(fmaxf(floorf(ty2), 0.0f), 127.0f);
        int x0 = (int)x0f, y0 = (int)y0f;
        int x1 = min(x0 + 1, 127), y1 = min(y0 + 1, 127);
        float wx = tx2 - x0f, wy = ty2 - y0f;
        const float* p00 = tex + (y0 * IMGS + x0) * 3;
        const float* p01 = tex + (y0 * IMGS + x1) * 3;
        const float* p10 = tex + (y1 * IMGS + x0) * 3;
        const float* p11 = tex + (y1 * IMGS + x1) * 3;
        float omwx = 1.0f - wx, omwy = 1.0f - wy;
        cr[t] = omwy * (omwx * __ldg(p00 + 0) + wx * __ldg(p01 + 0)) +
                wy   * (omwx * __ldg(p10 + 0) + wx * __ldg(p11 + 0));
        cg[t] = omwy * (omwx * __ldg(p00 + 1) + wx * __ldg(p01 + 1)) +
                wy   * (omwx * __ldg(p10 + 1) + wx * __ldg(p11 + 1));
        cb[t] = omwy * (omwx * __ldg(p00 + 2) + wx * __ldg(p01 + 2)) +
                wy   * (omwx * __ldg(p10 + 2) + wx * __ldg(p11 + 2));
        pr[t]  = __frcp_rn(1.0f + __expf(sdist * 1e4f));   // sigmoid(-d/SIGMA)
        zsv[t] = zpix;
        zin[t] = (100.0f - zpix) * R99;
    }

    // --- zmax: quad set-max over recomputed zinv (covers all 8 selected) ---
    float zmax = fmaxf(1e-10f, fmaxf(zin[0], zin[1]));
#pragma unroll
    for (int d = 1; d <= 2; d <<= 1)
        zmax = fmaxf(zmax, __shfl_xor_sync(0xffffffffu, zmax, d));
    float delta = __expf((1e-10f - zmax) * 1e4f);

    // --- weights + accumulate (invalid: pr=0, exp underflows to 0 -> w=0) ---
    float sw = 0.0f, sr = 0.0f, sg = 0.0f, sb = 0.0f, sd = 0.0f, ap = 1.0f;
#pragma unroll
    for (int t = 0; t < 2; t++) {
        float w = pr[t] * __expf((zin[t] - zmax) * 1e4f);
        sw += w;
        sr += w * cr[t];
        sg += w * cg[t];
        sb += w * cb[t];
        sd += w * zsv[t];
        ap *= (1.0f - pr[t]);
    }

    // --- quad butterfly reduction ---
#pragma unroll
    for (int d = 1; d <= 2; d <<= 1) {
        sw += __shfl_xor_sync(0xffffffffu, sw, d);
        sr += __shfl_xor_sync(0xffffffffu, sr, d);
        sg += __shfl_xor_sync(0xffffffffu, sg, d);
        sb += __shfl_xor_sync(0xffffffffu, sb, d);
        sd += __shfl_xor_sync(0xffffffffu, sd, d);
        ap *= __shfl_xor_sync(0xffffffffu, ap, d);
    }
    float rdenom = __frcp_rn(sw + delta);

    int o = (iy * IMGS + ix) * 5;
    if (sub == 0) {
        out[o + 0] = sr * rdenom;
        out[o + 4] = (sd + delta * 100.0f) * rdenom;
    } else if (sub == 1) {
        out[o + 1] = sg * rdenom;
    } else if (sub == 2) {
        out[o + 2] = sb * rdenom;
    } else {
        out[o + 3] = 1.0f - ap;
    }
}

extern "C" void kernel_launch(void* const* d_in, const int* in_sizes, int n_in,
                              void* d_out, int out_size) {
    (void)in_sizes; (void)n_in; (void)out_size;
    nvp_kernel<<<256, NTH>>>(
        (const float*)d_in[0],   // xy_offset (1,289,2)
        (const float*)d_in[1],   // z_grid    (1,289,1)
        (const float*)d_in[2],   // rgb_in    (1,128,128,3)
        (const float*)d_in[3],   // R_in      (1,3,3)
        (const float*)d_in[4],   // T_in      (1,3)
        (const float*)d_in[5],   // R_out     (1,3,3)
        (const float*)d_in[6],   // T_out     (1,3)
        (float*)d_out);          // (1,128,128,5) float32
}